// round 11
// baseline (speedup 1.0000x reference)
#include <cuda_runtime.h>

// ---------------- problem constants ----------------
static const int N0n = 32768;
static const int N1n = 8192;
static const int N2n = 2048;
static const int E0n = N0n * 8;
static const int E1n = N1n * 8;
static const int E2n = N2n * 8;
#define SLOTE 40
#define SLOTC 32
#define XS 128  // floats per node row (32 lanes x float4)
static const int N0S = N0n * SLOTE;
static const int N1S = N1n * SLOTE;
static const int N2S = N2n * SLOTE;

// ---------------- device scratch (static, no allocation) ----------------
__device__ float g_xA[N0n * XS];
__device__ float g_xB[N0n * XS];
__device__ float g_x0s[N0n * XS];
__device__ float g_x1s[N1n * XS];
__device__ float g_pos1[N1n * 3];
__device__ float g_pos2[N2n * 3];
__device__ float g_G[8 * 1024];  // precomputed gram matrices (scaled)
__device__ float4 g_ep0[E0n];    // {bitcast(src), rel.xyz} in edge order
__device__ float4 g_ep1[E1n];
__device__ float4 g_ep2[E2n];
__device__ float4 g_ge0[N0S];  // node-major sorted edge records
__device__ float4 g_ge1[N1S];
__device__ float4 g_ge2[N2S];
__device__ float g_rad0[4 * N0S];  // per-layer per-edge radial bias, level 0: L0,L1,L8,L9
__device__ float g_rad1[4 * N1S];  // level 1: L2,L3,L6,L7
__device__ float g_rad2[2 * N2S];  // level 2: L4,L5
__device__ int g_esl0[N0S];
__device__ int g_esl1[N1S];
__device__ int g_esl2[N2S];
__device__ int g_csl1[N1n * SLOTC];
__device__ int g_csl2[N2n * SLOTC];
__device__ int g_cnts[N0n + N1n + N2n + N1n + N2n];
__device__ int g_inv1[N0n];
__device__ int g_inv2[N1n];

// ---------------- helpers ----------------
__device__ __forceinline__ float warp_sum(float v) {
#pragma unroll
    for (int off = 16; off; off >>= 1) v += __shfl_xor_sync(0xffffffffu, v, off);
    return v;
}

// ---------------- build kernel 0: zero + grams + pooled positions + inv init ----------
__global__ void k_pre(const float* __restrict__ Wq_mid, const float* __restrict__ Wk_mid,
                      float* __restrict__ G, const float* __restrict__ pos0,
                      const int* __restrict__ fp1, const int* __restrict__ fp2, float* pos1,
                      float* pos2, int* cnts, int* inv1, int* inv2, float scl) {
    int i = blockIdx.x * blockDim.x + threadIdx.x;
    const int nCnt = N0n + N1n + N2n + N1n + N2n;
    if (i < nCnt) { cnts[i] = 0; return; }
    i -= nCnt;
    if (i < N0n) { inv1[i] = -1; return; }
    i -= N0n;
    if (i < N1n) { inv2[i] = -1; return; }
    i -= N1n;
    if (i < 8 * 1024) {
        int l = i >> 10, r = i & 1023, c = r >> 5, o = r & 31;
        const float* wq = Wq_mid + l * 1024 + c * 32;
        const float* wk = Wk_mid + l * 1024 + o * 32;
        float g = 0.f;
#pragma unroll
        for (int j = 0; j < 32; j++) g += wq[j] * wk[j];
        G[i] = g * scl;
        return;
    }
    i -= 8 * 1024;
    if (i < N1n * 3) {
        int node = i / 3, c = i % 3;
        pos1[i] = pos0[fp1[node] * 3 + c];
        return;
    }
    i -= N1n * 3;
    if (i < N2n * 3) {
        int node = i / 3, c = i % 3;
        pos2[i] = pos0[fp1[fp2[node]] * 3 + c];
    }
}

// ---------------- build kernel 1: slot scatter + edge geometry + inv build ------------
__device__ __forceinline__ void eg_one(const float* pos, int s, int d, float4* ep, int e) {
    float a = pos[d * 3 + 0] - pos[s * 3 + 0];
    float b = pos[d * 3 + 1] - pos[s * 3 + 1];
    float c = pos[d * 3 + 2] - pos[s * 3 + 2];
    ep[e] = make_float4(__int_as_float(s), a, b, c);
}

__global__ void k_scat_eg(const int* __restrict__ dst0, const int* __restrict__ dst1,
                          const int* __restrict__ dst2, const int* __restrict__ cl1,
                          const int* __restrict__ cl2, int* dE0, int* dE1, int* dE2,
                          int* dC1, int* dC2, int* esl0, int* esl1, int* esl2, int* csl1,
                          int* csl2, const float* __restrict__ pos0,
                          const float* __restrict__ pos1, const float* __restrict__ pos2,
                          const int* __restrict__ s0, const int* __restrict__ s1,
                          const int* __restrict__ s2, float4* ep0, float4* ep1, float4* ep2,
                          const int* __restrict__ fp1, const int* __restrict__ fp2,
                          int* inv1, int* inv2) {
    int i = blockIdx.x * blockDim.x + threadIdx.x;
    if (i < E0n) {
        int k = dst0[i];
        int p = atomicAdd(&dE0[k], 1);
        if (p < SLOTE) esl0[k * SLOTE + p] = i;
        return;
    }
    i -= E0n;
    if (i < E1n) {
        int k = dst1[i];
        int p = atomicAdd(&dE1[k], 1);
        if (p < SLOTE) esl1[k * SLOTE + p] = i;
        return;
    }
    i -= E1n;
    if (i < E2n) {
        int k = dst2[i];
        int p = atomicAdd(&dE2[k], 1);
        if (p < SLOTE) esl2[k * SLOTE + p] = i;
        return;
    }
    i -= E2n;
    if (i < N0n) {
        int k = cl1[i];
        int p = atomicAdd(&dC1[k], 1);
        if (p < SLOTC) csl1[k * SLOTC + p] = i;
        return;
    }
    i -= N0n;
    if (i < N1n) {
        int k = cl2[i];
        int p = atomicAdd(&dC2[k], 1);
        if (p < SLOTC) csl2[k * SLOTC + p] = i;
        return;
    }
    i -= N1n;
    if (i < E0n) { eg_one(pos0, s0[i], dst0[i], ep0, i); return; }
    i -= E0n;
    if (i < E1n) { eg_one(pos1, s1[i], dst1[i], ep1, i); return; }
    i -= E1n;
    if (i < E2n) { eg_one(pos2, s2[i], dst2[i], ep2, i); return; }
    i -= E2n;
    if (i < N1n) { inv1[fp1[i]] = i; return; }
    i -= N1n;
    if (i < N2n) { inv2[fp2[i]] = i; }
}

// ---------------- build kernel 2: sort + materialize + PER-LAYER RADIAL BIAS ----------
template <int NL, int A, int B, int C, int D>
__device__ __forceinline__ void finedge_rad(int* slot, const int* cnt, const float4* ep,
                                            float4* ge, float* rad, int stride,
                                            const float* wr1, const float* wr2, int node) {
    int deg = min(cnt[node], SLOTE);
    int base = node * SLOTE;
    for (int a = 1; a < deg; a++) {
        int v = slot[base + a];
        int b = a - 1;
        while (b >= 0 && slot[base + b] > v) { slot[base + b + 1] = slot[base + b]; b--; }
        slot[base + b + 1] = v;
    }
    const int li[4] = {A, B, C, D};
    for (int j = 0; j < deg; j++) {
        float4 e = ep[slot[base + j]];
        ge[base + j] = e;
        float rr = sqrtf(e.y * e.y + e.z * e.z + e.w * e.w + 1e-12f);
#pragma unroll
        for (int l = 0; l < NL; l++) {
            const float* w1 = wr1 + 16 * li[l];
            const float* w2 = wr2 + 16 * li[l];
            float r = 0.f;
#pragma unroll
            for (int k = 0; k < 16; k++) r += fmaxf(rr * w1[k], 0.f) * w2[k];
            rad[l * stride + base + j] = r;
        }
    }
}

__device__ __forceinline__ void sortc_one(int* slot, const int* cnt, int node) {
    int deg = min(cnt[node], SLOTC);
    int base = node * SLOTC;
    for (int a = 1; a < deg; a++) {
        int v = slot[base + a];
        int b = a - 1;
        while (b >= 0 && slot[base + b] > v) { slot[base + b + 1] = slot[base + b]; b--; }
        slot[base + b + 1] = v;
    }
}

__global__ void k_finsort_all(int* esl0, int* esl1, int* esl2, int* csl1, int* csl2,
                              const int* __restrict__ dE0, const int* __restrict__ dE1,
                              const int* __restrict__ dE2, const int* __restrict__ dC1,
                              const int* __restrict__ dC2, const float4* __restrict__ ep0,
                              const float4* __restrict__ ep1, const float4* __restrict__ ep2,
                              float4* ge0, float4* ge1, float4* ge2, float* rad0,
                              float* rad1, float* rad2, const float* __restrict__ wr1,
                              const float* __restrict__ wr2) {
    int i = blockIdx.x * blockDim.x + threadIdx.x;
    if (i < N0n) {
        finedge_rad<4, 0, 1, 8, 9>(esl0, dE0, ep0, ge0, rad0, N0S, wr1, wr2, i);
        return;
    }
    i -= N0n;
    if (i < N1n) {
        finedge_rad<4, 2, 3, 6, 7>(esl1, dE1, ep1, ge1, rad1, N1S, wr1, wr2, i);
        return;
    }
    i -= N1n;
    if (i < N2n) {
        finedge_rad<2, 4, 5, 0, 0>(esl2, dE2, ep2, ge2, rad2, N2S, wr1, wr2, i);
        return;
    }
    i -= N2n;
    if (i < N1n) { sortc_one(csl1, dC1, i); return; }
    i -= N1n;
    if (i < N2n) { sortc_one(csl2, dC2, i); }
}

// ---------------- layer 0: 8-threads-per-node attention (Cin=1 -> Co=32) --------------
__global__ __launch_bounds__(256) void k_attn0(
    const float* __restrict__ x, const float4* __restrict__ ge, const int* __restrict__ cnt,
    const float* __restrict__ radp, const float* __restrict__ Wq,
    const float* __restrict__ Wk, const float* __restrict__ Wv, const float* __restrict__ Ws,
    const float* __restrict__ scale, const float* __restrict__ bias,
    float* __restrict__ outp, int n, float scl) {
    __shared__ float sGs;
    __shared__ float sZ[32];
    __shared__ float sS1[32][3];
    __shared__ float sS2[32][3];
    __shared__ float sXd[32][3];
    int tid = threadIdx.x;
    if (tid == 0) {
        float g = 0.f;
#pragma unroll
        for (int j = 0; j < 32; j++) g += Wq[j] * Wk[j];
        sGs = g * scl;
    }
    __syncthreads();
    int group = tid >> 3, gl = tid & 7;
    int node = blockIdx.x * 32 + group;
    if (node < n) {
        float Gs = sGs;
        float xd0 = x[node * 3 + 0], xd1 = x[node * 3 + 1], xd2 = x[node * 3 + 2];
        int deg = min(cnt[node], SLOTE);
        int base = node * SLOTE;
        float z = 0.f, s10 = 0.f, s11 = 0.f, s12 = 0.f, s20 = 0.f, s21 = 0.f, s22 = 0.f;
        for (int j = gl; j < deg; j += 8) {
            float4 e = ge[base + j];
            float rad = radp[base + j];
            int s = __float_as_int(e.x);
            float xs0 = x[s * 3 + 0], xs1 = x[s * 3 + 1], xs2 = x[s * 3 + 2];
            float w = __expf(Gs * (xd0 * xs0 + xd1 * xs1 + xd2 * xs2) + rad);
            z += w;
            s10 += w * xs0;
            s11 += w * xs1;
            s12 += w * xs2;
            s20 += w * e.y;
            s21 += w * e.z;
            s22 += w * e.w;
        }
#pragma unroll
        for (int off = 4; off; off >>= 1) {
            z += __shfl_xor_sync(0xffffffffu, z, off);
            s10 += __shfl_xor_sync(0xffffffffu, s10, off);
            s11 += __shfl_xor_sync(0xffffffffu, s11, off);
            s12 += __shfl_xor_sync(0xffffffffu, s12, off);
            s20 += __shfl_xor_sync(0xffffffffu, s20, off);
            s21 += __shfl_xor_sync(0xffffffffu, s21, off);
            s22 += __shfl_xor_sync(0xffffffffu, s22, off);
        }
        if (gl == 0) {
            sZ[group] = z;
            sS1[group][0] = s10; sS1[group][1] = s11; sS1[group][2] = s12;
            sS2[group][0] = s20; sS2[group][1] = s21; sS2[group][2] = s22;
            sXd[group][0] = xd0; sXd[group][1] = xd1; sXd[group][2] = xd2;
        }
    }
    __syncthreads();
    int warp = tid >> 5, lane = tid & 31;
    float wv = Wv[lane], ws = Ws[lane];
    float sc = scale[lane], bi = bias[lane];
    int blockBase = blockIdx.x * 32;
    for (int i = warp; i < 32; i += 8) {
        int nd = blockBase + i;
        if (nd >= n) break;
        float invz = 1.f / (sZ[i] + 1e-9f);
        float a0 = (wv * sS1[i][0] + sS2[i][0]) * invz + ws * sXd[i][0];
        float a1 = (wv * sS1[i][1] + sS2[i][1]) * invz + ws * sXd[i][1];
        float a2 = (wv * sS1[i][2] + sS2[i][2]) * invz + ws * sXd[i][2];
        float nrm = sqrtf(a0 * a0 + a1 * a1 + a2 * a2 + 1e-12f);
        float t = fmaxf(sc * nrm + bi, 0.f);
        float f = t / nrm;
        *(float4*)(outp + (size_t)nd * XS + lane * 4) =
            make_float4(a0 * f, a1 * f, a2 * f, 0.f);
    }
}

// ---------------- fused attention (Cin=32, rad precomputed, float4 LDS) --------------
template <int Co>
__global__ __launch_bounds__(256) void k_attnF(
    const float* __restrict__ x, const float4* __restrict__ ge, const int* __restrict__ cnt,
    const float* __restrict__ radp, const float* __restrict__ Gbuf,
    const float* __restrict__ Wq, const float* __restrict__ Wk, const float* __restrict__ Wv,
    const float* __restrict__ Ws, const float* __restrict__ scale,
    const float* __restrict__ bias, float* __restrict__ outp, int n, float scl) {
    __shared__ float sG[(Co == 32) ? 1024 : 1];
    __shared__ float sWv[(Co == 32) ? 1024 : 1];
    __shared__ float sWs[(Co == 32) ? 1024 : 1];
    __shared__ __align__(16) float sXd[8][(Co == 32) ? 96 : 4];
    __shared__ __align__(16) float sAx[8][(Co == 32) ? 96 : 4];
    int tid = threadIdx.x, warp = tid >> 5, lane = tid & 31;
    if (Co == 32) {
        for (int i = tid; i < 1024; i += 256) {
            sG[i] = Gbuf[i];
            sWv[i] = Wv[i];
            sWs[i] = Ws[i];
        }
        __syncthreads();
    }
    for (int node = blockIdx.x * 8 + warp; node < n; node += gridDim.x * 8) {
        float4 xd4 = *(const float4*)(x + (size_t)node * XS + lane * 4);
        float xd0 = xd4.x, xd1 = xd4.y, xd2 = xd4.z;
        float q0, q1, q2;
        if (Co == 32) {
            sXd[warp][lane] = xd0;
            sXd[warp][32 + lane] = xd1;
            sXd[warp][64 + lane] = xd2;
            __syncwarp();
            const float4* xp4 = (const float4*)sXd[warp];
            q0 = q1 = q2 = 0.f;
#pragma unroll
            for (int c4 = 0; c4 < 8; c4++) {
                float4 x0 = xp4[c4], x1 = xp4[8 + c4], x2 = xp4[16 + c4];
                float ga = sG[(c4 * 4 + 0) * 32 + lane];
                float gb = sG[(c4 * 4 + 1) * 32 + lane];
                float gc = sG[(c4 * 4 + 2) * 32 + lane];
                float gd = sG[(c4 * 4 + 3) * 32 + lane];
                q0 += ga * x0.x + gb * x0.y + gc * x0.z + gd * x0.w;
                q1 += ga * x1.x + gb * x1.y + gc * x1.z + gd * x1.w;
                q2 += ga * x2.x + gb * x2.y + gc * x2.z + gd * x2.w;
            }
        } else {
            float wq = Wq[lane];
            float d0 = warp_sum(xd0 * wq);
            float d1 = warp_sum(xd1 * wq);
            float d2 = warp_sum(xd2 * wq);
            float f = scl * Wk[lane];
            q0 = f * d0;
            q1 = f * d1;
            q2 = f * d2;
        }
        int deg = min(cnt[node], SLOTE);
        int base = node * SLOTE;
        float z = 0.f, ax0 = 0.f, ax1 = 0.f, ax2 = 0.f, rs0 = 0.f, rs1 = 0.f, rs2 = 0.f;
        int j = 0;
        for (; j + 4 <= deg; j += 4) {
            float4 e0 = ge[base + j];
            float4 e1 = ge[base + j + 1];
            float4 e2 = ge[base + j + 2];
            float4 e3 = ge[base + j + 3];
            float4 rv = *(const float4*)(radp + base + j);
            float4 xa = *(const float4*)(x + (size_t)__float_as_int(e0.x) * XS + lane * 4);
            float4 xb = *(const float4*)(x + (size_t)__float_as_int(e1.x) * XS + lane * 4);
            float4 xc = *(const float4*)(x + (size_t)__float_as_int(e2.x) * XS + lane * 4);
            float4 xd = *(const float4*)(x + (size_t)__float_as_int(e3.x) * XS + lane * 4);
            float p0 = q0 * xa.x + q1 * xa.y + q2 * xa.z;
            float p1 = q0 * xb.x + q1 * xb.y + q2 * xb.z;
            float p2 = q0 * xc.x + q1 * xc.y + q2 * xc.z;
            float p3 = q0 * xd.x + q1 * xd.y + q2 * xd.z;
#pragma unroll
            for (int off = 16; off; off >>= 1) {
                p0 += __shfl_xor_sync(0xffffffffu, p0, off);
                p1 += __shfl_xor_sync(0xffffffffu, p1, off);
                p2 += __shfl_xor_sync(0xffffffffu, p2, off);
                p3 += __shfl_xor_sync(0xffffffffu, p3, off);
            }
            float w0 = __expf(p0 + rv.x), w1f = __expf(p1 + rv.y);
            float w2f = __expf(p2 + rv.z), w3f = __expf(p3 + rv.w);
            z += (w0 + w1f) + (w2f + w3f);
            rs0 += w0 * e0.y + w1f * e1.y + w2f * e2.y + w3f * e3.y;
            rs1 += w0 * e0.z + w1f * e1.z + w2f * e2.z + w3f * e3.z;
            rs2 += w0 * e0.w + w1f * e1.w + w2f * e2.w + w3f * e3.w;
            ax0 += w0 * xa.x + w1f * xb.x + w2f * xc.x + w3f * xd.x;
            ax1 += w0 * xa.y + w1f * xb.y + w2f * xc.y + w3f * xd.y;
            ax2 += w0 * xa.z + w1f * xb.z + w2f * xc.z + w3f * xd.z;
        }
        for (; j < deg; j++) {
            float4 e0 = ge[base + j];
            float4 xa = *(const float4*)(x + (size_t)__float_as_int(e0.x) * XS + lane * 4);
            float p0 = warp_sum(q0 * xa.x + q1 * xa.y + q2 * xa.z);
            float w0 = __expf(p0 + radp[base + j]);
            z += w0;
            rs0 += w0 * e0.y;
            rs1 += w0 * e0.z;
            rs2 += w0 * e0.w;
            ax0 += w0 * xa.x;
            ax1 += w0 * xa.y;
            ax2 += w0 * xa.z;
        }
        float invz = 1.f / (z + 1e-9f);
        if (Co == 32) {
            sAx[warp][lane] = ax0;
            sAx[warp][32 + lane] = ax1;
            sAx[warp][64 + lane] = ax2;
            __syncwarp();
            const float4* ap4 = (const float4*)sAx[warp];
            const float4* xp4 = (const float4*)sXd[warp];
            float v0 = 0.f, v1 = 0.f, v2 = 0.f, sk0 = 0.f, sk1 = 0.f, sk2 = 0.f;
#pragma unroll
            for (int c4 = 0; c4 < 8; c4++) {
                float4 a0v = ap4[c4], a1v = ap4[8 + c4], a2v = ap4[16 + c4];
                float4 x0v = xp4[c4], x1v = xp4[8 + c4], x2v = xp4[16 + c4];
                float wa = sWv[(c4 * 4 + 0) * 32 + lane];
                float wb = sWv[(c4 * 4 + 1) * 32 + lane];
                float wc = sWv[(c4 * 4 + 2) * 32 + lane];
                float wd = sWv[(c4 * 4 + 3) * 32 + lane];
                float sa = sWs[(c4 * 4 + 0) * 32 + lane];
                float sb = sWs[(c4 * 4 + 1) * 32 + lane];
                float scc = sWs[(c4 * 4 + 2) * 32 + lane];
                float sd = sWs[(c4 * 4 + 3) * 32 + lane];
                v0 += wa * a0v.x + wb * a0v.y + wc * a0v.z + wd * a0v.w;
                v1 += wa * a1v.x + wb * a1v.y + wc * a1v.z + wd * a1v.w;
                v2 += wa * a2v.x + wb * a2v.y + wc * a2v.z + wd * a2v.w;
                sk0 += sa * x0v.x + sb * x0v.y + scc * x0v.z + sd * x0v.w;
                sk1 += sa * x1v.x + sb * x1v.y + scc * x1v.z + sd * x1v.w;
                sk2 += sa * x2v.x + sb * x2v.y + scc * x2v.z + sd * x2v.w;
            }
            float a0 = (v0 + rs0) * invz + sk0;
            float a1 = (v1 + rs1) * invz + sk1;
            float a2 = (v2 + rs2) * invz + sk2;
            float sc = scale[lane], bi = bias[lane];
            float nrm = sqrtf(a0 * a0 + a1 * a1 + a2 * a2 + 1e-12f);
            float t = fmaxf(sc * nrm + bi, 0.f);
            float f = t / nrm;
            *(float4*)(outp + (size_t)node * XS + lane * 4) =
                make_float4(a0 * f, a1 * f, a2 * f, 0.f);
            __syncwarp();
        } else {
            float wv = Wv[lane], ws = Ws[lane];
            float v0 = warp_sum(wv * ax0);
            float v1 = warp_sum(wv * ax1);
            float v2 = warp_sum(wv * ax2);
            float sk0 = warp_sum(ws * xd0);
            float sk1 = warp_sum(ws * xd1);
            float sk2 = warp_sum(ws * xd2);
            if (lane == 0) {
                float a0 = (v0 + rs0) * invz + sk0;
                float a1 = (v1 + rs1) * invz + sk1;
                float a2 = (v2 + rs2) * invz + sk2;
                float sc = scale[0], bi = bias[0];
                float nrm = sqrtf(a0 * a0 + a1 * a1 + a2 * a2 + 1e-12f);
                float t = fmaxf(sc * nrm + bi, 0.f);
                float f = t / nrm;
                outp[node * 3 + 0] = a0 * f;
                outp[node * 3 + 1] = a1 * f;
                outp[node * 3 + 2] = a2 * f;
            }
        }
    }
}

// ---------------- pooling / upsample / head ----------------
__global__ void k_segmean(const float* __restrict__ xin, const int* __restrict__ cnt,
                          const int* __restrict__ csl, float* __restrict__ outp, int nseg) {
    int warp = (blockIdx.x * blockDim.x + threadIdx.x) >> 5;
    int lane = threadIdx.x & 31;
    if (warp >= nseg) return;
    int deg = min(cnt[warp], SLOTC);
    int base = warp * SLOTC;
    float a0 = 0.f, a1 = 0.f, a2 = 0.f;
    for (int j = 0; j < deg; j++) {
        int mnode = csl[base + j];
        float4 xv = *(const float4*)(xin + (size_t)mnode * XS + lane * 4);
        a0 += xv.x;
        a1 += xv.y;
        a2 += xv.z;
    }
    float inv = 1.f / ((float)deg + 1e-9f);
    *(float4*)(outp + (size_t)warp * XS + lane * 4) =
        make_float4(a0 * inv, a1 * inv, a2 * inv, 0.f);
}

__global__ void k_upsample(float* __restrict__ outp, const float* __restrict__ basep,
                           const int* __restrict__ inv, const float* __restrict__ xup,
                           int n) {
    int i = blockIdx.x * blockDim.x + threadIdx.x;
    if (i >= n * XS) return;
    int node = i >> 7, t = i & (XS - 1);
    int s = inv[node];
    float v = basep[i];
    if (s >= 0) v += xup[(size_t)s * XS + t];
    outp[i] = v;
}

__global__ void k_mlp(const float* __restrict__ xin, const float* __restrict__ W,
                      float* __restrict__ outp, int n) {
    int i = blockIdx.x * blockDim.x + threadIdx.x;
    if (i >= n * 40) return;
    int node = i / 40, o = i % 40;
    float s = xin[node * 3 + 0] * W[o] + xin[node * 3 + 1] * W[40 + o] +
              xin[node * 3 + 2] * W[80 + o];
    outp[i] = s > 0.f ? s : 0.f;
}

// ---------------- host orchestration ----------------
#define GETSYM(p, s)                  \
    do {                              \
        void* _t;                     \
        cudaGetSymbolAddress(&_t, s); \
        p = (decltype(p))_t;          \
    } while (0)

extern "C" void kernel_launch(void* const* d_in, const int* in_sizes, int n_in,
                              void* d_out, int out_size) {
    const float* pos0 = (const float*)d_in[0];
    const float* v0 = (const float*)d_in[1];
    const float* Wq_first = (const float*)d_in[2];
    const float* Wk_first = (const float*)d_in[3];
    const float* Wv_first = (const float*)d_in[4];
    const float* Ws_first = (const float*)d_in[5];
    const float* Wq_mid = (const float*)d_in[6];
    const float* Wk_mid = (const float*)d_in[7];
    const float* Wv_mid = (const float*)d_in[8];
    const float* Ws_mid = (const float*)d_in[9];
    const float* Wq_last = (const float*)d_in[10];
    const float* Wk_last = (const float*)d_in[11];
    const float* Wv_last = (const float*)d_in[12];
    const float* Ws_last = (const float*)d_in[13];
    const float* wr1 = (const float*)d_in[14];
    const float* wr2 = (const float*)d_in[15];
    const float* scale_mid = (const float*)d_in[16];
    const float* bias_mid = (const float*)d_in[17];
    const float* scale_last = (const float*)d_in[18];
    const float* bias_last = (const float*)d_in[19];
    const float* Wmlp = (const float*)d_in[20];
    const int* src0 = (const int*)d_in[21];
    const int* dst0 = (const int*)d_in[22];
    const int* src1 = (const int*)d_in[23];
    const int* dst1 = (const int*)d_in[24];
    const int* src2 = (const int*)d_in[25];
    const int* dst2 = (const int*)d_in[26];
    const int* fp1 = (const int*)d_in[27];
    const int* fp2 = (const int*)d_in[28];
    const int* cl1 = (const int*)d_in[29];
    const int* cl2 = (const int*)d_in[30];
    float* outp = (float*)d_out;

    float *xA, *xB, *x0s, *x1s, *pos1, *pos2, *Gb, *rad0, *rad1, *rad2;
    float4 *ep0, *ep1, *ep2, *ge0, *ge1, *ge2;
    int *cnts, *esl0, *esl1, *esl2, *csl1, *csl2, *inv1, *inv2;
    GETSYM(xA, g_xA); GETSYM(xB, g_xB); GETSYM(x0s, g_x0s); GETSYM(x1s, g_x1s);
    GETSYM(pos1, g_pos1); GETSYM(pos2, g_pos2); GETSYM(Gb, g_G);
    GETSYM(rad0, g_rad0); GETSYM(rad1, g_rad1); GETSYM(rad2, g_rad2);
    GETSYM(ep0, g_ep0); GETSYM(ep1, g_ep1); GETSYM(ep2, g_ep2);
    GETSYM(ge0, g_ge0); GETSYM(ge1, g_ge1); GETSYM(ge2, g_ge2);
    GETSYM(esl0, g_esl0); GETSYM(esl1, g_esl1); GETSYM(esl2, g_esl2);
    GETSYM(csl1, g_csl1); GETSYM(csl2, g_csl2);
    GETSYM(cnts, g_cnts); GETSYM(inv1, g_inv1); GETSYM(inv2, g_inv2);

    int* dE0 = cnts;
    int* dE1 = cnts + N0n;
    int* dE2 = cnts + N0n + N1n;
    int* dC1 = cnts + N0n + N1n + N2n;
    int* dC2 = cnts + N0n + N1n + N2n + N1n;
    const int nCnt = N0n + N1n + N2n + N1n + N2n;

    const float scl_mid = 0.10206207261596575f;  // 1/sqrt(96)
    const float scl_last = 0.5773502691896258f;  // 1/sqrt(3)
    auto midW = [&](const float* base, int i) { return base + i * 32 * 32; };

    // ---- build: 3 launches ----
    {
        int tot = nCnt + N0n + N1n + 8 * 1024 + N1n * 3 + N2n * 3;
        k_pre<<<(tot + 255) / 256, 256>>>(Wq_mid, Wk_mid, Gb, pos0, fp1, fp2, pos1, pos2,
                                          cnts, inv1, inv2, scl_mid);
    }
    {
        int tot = E0n + E1n + E2n + N0n + N1n + E0n + E1n + E2n + N1n + N2n;
        k_scat_eg<<<(tot + 255) / 256, 256>>>(dst0, dst1, dst2, cl1, cl2, dE0, dE1, dE2,
                                              dC1, dC2, esl0, esl1, esl2, csl1, csl2, pos0,
                                              pos1, pos2, src0, src1, src2, ep0, ep1, ep2,
                                              fp1, fp2, inv1, inv2);
    }
    {
        int tot = N0n + N1n + N2n + N1n + N2n;
        k_finsort_all<<<(tot + 255) / 256, 256>>>(esl0, esl1, esl2, csl1, csl2, dE0, dE1,
                                                  dE2, dC1, dC2, ep0, ep1, ep2, ge0, ge1,
                                                  ge2, rad0, rad1, rad2, wr1, wr2);
    }

    // ---- layer 0 (launch index 3 — ncu capture target) ----
    k_attn0<<<(N0n + 31) / 32, 256>>>(v0, ge0, dE0, rad0, Wq_first, Wk_first, Wv_first,
                                      Ws_first, scale_mid + 0, bias_mid + 0, xA, N0n,
                                      scl_mid);

    struct LD {
        int n;
        const int* cnt;
        const float4* ge;
        const float* rad;
        const float *Gq, *Wq, *Wk, *Wv, *Ws, *sc, *bi;
        const float* xin;
        float* xout;
        float scl;
        int co;
    };
    LD L[10];
    L[1] = {N0n, dE0, ge0, rad0 + 1 * N0S, Gb + 0 * 1024, midW(Wq_mid, 0), midW(Wk_mid, 0),
            midW(Wv_mid, 0), midW(Ws_mid, 0), scale_mid + 32, bias_mid + 32, xA, x0s,
            scl_mid, 32};
    L[2] = {N1n, dE1, ge1, rad1 + 0 * N1S, Gb + 1 * 1024, midW(Wq_mid, 1), midW(Wk_mid, 1),
            midW(Wv_mid, 1), midW(Ws_mid, 1), scale_mid + 64, bias_mid + 64, xA, xB,
            scl_mid, 32};
    L[3] = {N1n, dE1, ge1, rad1 + 1 * N1S, Gb + 2 * 1024, midW(Wq_mid, 2), midW(Wk_mid, 2),
            midW(Wv_mid, 2), midW(Ws_mid, 2), scale_mid + 96, bias_mid + 96, xB, x1s,
            scl_mid, 32};
    L[4] = {N2n, dE2, ge2, rad2 + 0 * N2S, Gb + 3 * 1024, midW(Wq_mid, 3), midW(Wk_mid, 3),
            midW(Wv_mid, 3), midW(Ws_mid, 3), scale_mid + 128, bias_mid + 128, xA, xB,
            scl_mid, 32};
    L[5] = {N2n, dE2, ge2, rad2 + 1 * N2S, Gb + 4 * 1024, midW(Wq_mid, 4), midW(Wk_mid, 4),
            midW(Wv_mid, 4), midW(Ws_mid, 4), scale_mid + 160, bias_mid + 160, xB, xA,
            scl_mid, 32};
    L[6] = {N1n, dE1, ge1, rad1 + 2 * N1S, Gb + 5 * 1024, midW(Wq_mid, 5), midW(Wk_mid, 5),
            midW(Wv_mid, 5), midW(Ws_mid, 5), scale_mid + 192, bias_mid + 192, xB, xA,
            scl_mid, 32};
    L[7] = {N1n, dE1, ge1, rad1 + 3 * N1S, Gb + 6 * 1024, midW(Wq_mid, 6), midW(Wk_mid, 6),
            midW(Wv_mid, 6), midW(Ws_mid, 6), scale_mid + 224, bias_mid + 224, xA, xB,
            scl_mid, 32};
    L[8] = {N0n, dE0, ge0, rad0 + 2 * N0S, Gb + 7 * 1024, midW(Wq_mid, 7), midW(Wk_mid, 7),
            midW(Wv_mid, 7), midW(Ws_mid, 7), scale_mid + 256, bias_mid + 256, xA, xB,
            scl_mid, 32};
    L[9] = {N0n, dE0, ge0, rad0 + 3 * N0S, Gb, Wq_last, Wk_last, Wv_last, Ws_last,
            scale_last, bias_last, xB, xA, scl_last, 1};

    auto run_layer = [&](const LD& d) {
        int blk = (d.n + 7) / 8;  // full grid (persistent cap reverted)
        if (d.co == 32) {
            k_attnF<32><<<blk, 256>>>(d.xin, d.ge, d.cnt, d.rad, d.Gq, d.Wq, d.Wk, d.Wv,
                                      d.Ws, d.sc, d.bi, d.xout, d.n, d.scl);
        } else {
            k_attnF<1><<<blk, 256>>>(d.xin, d.ge, d.cnt, d.rad, d.Gq, d.Wq, d.Wk, d.Wv,
                                     d.Ws, d.sc, d.bi, d.xout, d.n, d.scl);
        }
    };

    run_layer(L[1]);  // -> x0s
    k_segmean<<<(N1n + 7) / 8, 256>>>(x0s, dC1, csl1, xA, N1n);
    run_layer(L[2]);
    run_layer(L[3]);  // -> x1s
    k_segmean<<<(N2n + 7) / 8, 256>>>(x1s, dC2, csl2, xA, N2n);
    run_layer(L[4]);
    run_layer(L[5]);  // -> xA (N2)
    k_upsample<<<(N1n * XS + 255) / 256, 256>>>(xB, x1s, inv2, xA, N1n);
    run_layer(L[6]);
    run_layer(L[7]);  // -> xB (N1)
    k_upsample<<<(N0n * XS + 255) / 256, 256>>>(xA, x0s, inv1, xB, N0n);
    run_layer(L[8]);
    run_layer(L[9]);  // -> xA [N0,3]
    k_mlp<<<(N0n * 40 + 255) / 256, 256>>>(xA, Wmlp, outp, N0n);
}

// round 12
// speedup vs baseline: 1.1945x; 1.1945x over previous
#include <cuda_runtime.h>

// ---------------- problem constants ----------------
static const int N0n = 32768;
static const int N1n = 8192;
static const int N2n = 2048;
static const int E0n = N0n * 8;
static const int E1n = N1n * 8;
static const int E2n = N2n * 8;
#define SLOTE 40
#define SLOTC 32
#define XS 128  // floats per node row (32 lanes x float4)

// ---------------- device scratch (static, no allocation) ----------------
__device__ float g_xA[N0n * XS];
__device__ float g_xB[N0n * XS];
__device__ float g_x0s[N0n * XS];
__device__ float g_x1s[N1n * XS];
__device__ float g_pos1[N1n * 3];
__device__ float g_pos2[N2n * 3];
__device__ float g_G[8 * 1024];  // precomputed gram matrices (scaled)
__device__ float4 g_ep0[E0n];    // {bitcast(src), rel.xyz} in edge order
__device__ float4 g_ep1[E1n];
__device__ float4 g_ep2[E2n];
__device__ float4 g_ge0[N0n * SLOTE];  // node-major sorted edge records
__device__ float4 g_ge1[N1n * SLOTE];
__device__ float4 g_ge2[N2n * SLOTE];
__device__ int g_esl0[N0n * SLOTE];
__device__ int g_esl1[N1n * SLOTE];
__device__ int g_esl2[N2n * SLOTE];
__device__ int g_csl1[N1n * SLOTC];
__device__ int g_csl2[N2n * SLOTC];
__device__ int g_cnts[N0n + N1n + N2n + N1n + N2n];
__device__ int g_inv1[N0n];  // level0 node -> level1 source (or -1)
__device__ int g_inv2[N1n];  // level1 node -> level2 source (or -1)

// ---------------- helpers ----------------
__device__ __forceinline__ float warp_sum(float v) {
#pragma unroll
    for (int off = 16; off; off >>= 1) v += __shfl_xor_sync(0xffffffffu, v, off);
    return v;
}

// ---------------- build kernel 0: zero + grams + pooled positions + inv init ----------
__global__ void k_pre(const float* __restrict__ Wq_mid, const float* __restrict__ Wk_mid,
                      float* __restrict__ G, const float* __restrict__ pos0,
                      const int* __restrict__ fp1, const int* __restrict__ fp2, float* pos1,
                      float* pos2, int* cnts, int* inv1, int* inv2, float scl) {
    int i = blockIdx.x * blockDim.x + threadIdx.x;
    const int nCnt = N0n + N1n + N2n + N1n + N2n;
    if (i < nCnt) { cnts[i] = 0; return; }
    i -= nCnt;
    if (i < N0n) { inv1[i] = -1; return; }
    i -= N0n;
    if (i < N1n) { inv2[i] = -1; return; }
    i -= N1n;
    if (i < 8 * 1024) {
        int l = i >> 10, r = i & 1023, c = r >> 5, o = r & 31;
        const float* wq = Wq_mid + l * 1024 + c * 32;
        const float* wk = Wk_mid + l * 1024 + o * 32;
        float g = 0.f;
#pragma unroll
        for (int j = 0; j < 32; j++) g += wq[j] * wk[j];
        G[i] = g * scl;
        return;
    }
    i -= 8 * 1024;
    if (i < N1n * 3) {
        int node = i / 3, c = i % 3;
        pos1[i] = pos0[fp1[node] * 3 + c];
        return;
    }
    i -= N1n * 3;
    if (i < N2n * 3) {
        int node = i / 3, c = i % 3;
        pos2[i] = pos0[fp1[fp2[node]] * 3 + c];
    }
}

// ---------------- build kernel 1: slot scatter + edge geometry + inv build ------------
__device__ __forceinline__ void eg_one(const float* pos, int s, int d, float4* ep, int e) {
    float a = pos[d * 3 + 0] - pos[s * 3 + 0];
    float b = pos[d * 3 + 1] - pos[s * 3 + 1];
    float c = pos[d * 3 + 2] - pos[s * 3 + 2];
    ep[e] = make_float4(__int_as_float(s), a, b, c);
}

__global__ void k_scat_eg(const int* __restrict__ dst0, const int* __restrict__ dst1,
                          const int* __restrict__ dst2, const int* __restrict__ cl1,
                          const int* __restrict__ cl2, int* dE0, int* dE1, int* dE2,
                          int* dC1, int* dC2, int* esl0, int* esl1, int* esl2, int* csl1,
                          int* csl2, const float* __restrict__ pos0,
                          const float* __restrict__ pos1, const float* __restrict__ pos2,
                          const int* __restrict__ s0, const int* __restrict__ s1,
                          const int* __restrict__ s2, float4* ep0, float4* ep1, float4* ep2,
                          const int* __restrict__ fp1, const int* __restrict__ fp2,
                          int* inv1, int* inv2) {
    int i = blockIdx.x * blockDim.x + threadIdx.x;
    if (i < E0n) {
        int k = dst0[i];
        int p = atomicAdd(&dE0[k], 1);
        if (p < SLOTE) esl0[k * SLOTE + p] = i;
        return;
    }
    i -= E0n;
    if (i < E1n) {
        int k = dst1[i];
        int p = atomicAdd(&dE1[k], 1);
        if (p < SLOTE) esl1[k * SLOTE + p] = i;
        return;
    }
    i -= E1n;
    if (i < E2n) {
        int k = dst2[i];
        int p = atomicAdd(&dE2[k], 1);
        if (p < SLOTE) esl2[k * SLOTE + p] = i;
        return;
    }
    i -= E2n;
    if (i < N0n) {
        int k = cl1[i];
        int p = atomicAdd(&dC1[k], 1);
        if (p < SLOTC) csl1[k * SLOTC + p] = i;
        return;
    }
    i -= N0n;
    if (i < N1n) {
        int k = cl2[i];
        int p = atomicAdd(&dC2[k], 1);
        if (p < SLOTC) csl2[k * SLOTC + p] = i;
        return;
    }
    i -= N1n;
    if (i < E0n) { eg_one(pos0, s0[i], dst0[i], ep0, i); return; }
    i -= E0n;
    if (i < E1n) { eg_one(pos1, s1[i], dst1[i], ep1, i); return; }
    i -= E1n;
    if (i < E2n) { eg_one(pos2, s2[i], dst2[i], ep2, i); return; }
    i -= E2n;
    if (i < N1n) { inv1[fp1[i]] = i; return; }
    i -= N1n;
    if (i < N2n) { inv2[fp2[i]] = i; }
}

// ---------------- build kernel 2: per-node sort + edge record materialize -------------
__device__ __forceinline__ void finedge_one(int* slot, const int* cnt, const float4* ep,
                                            float4* ge, int node) {
    int deg = min(cnt[node], SLOTE);
    int base = node * SLOTE;
    for (int a = 1; a < deg; a++) {
        int v = slot[base + a];
        int b = a - 1;
        while (b >= 0 && slot[base + b] > v) { slot[base + b + 1] = slot[base + b]; b--; }
        slot[base + b + 1] = v;
    }
    for (int j = 0; j < deg; j++) ge[base + j] = ep[slot[base + j]];
}

__device__ __forceinline__ void sortc_one(int* slot, const int* cnt, int node) {
    int deg = min(cnt[node], SLOTC);
    int base = node * SLOTC;
    for (int a = 1; a < deg; a++) {
        int v = slot[base + a];
        int b = a - 1;
        while (b >= 0 && slot[base + b] > v) { slot[base + b + 1] = slot[base + b]; b--; }
        slot[base + b + 1] = v;
    }
}

__global__ void k_finsort_all(int* esl0, int* esl1, int* esl2, int* csl1, int* csl2,
                              const int* __restrict__ dE0, const int* __restrict__ dE1,
                              const int* __restrict__ dE2, const int* __restrict__ dC1,
                              const int* __restrict__ dC2, const float4* __restrict__ ep0,
                              const float4* __restrict__ ep1, const float4* __restrict__ ep2,
                              float4* ge0, float4* ge1, float4* ge2) {
    int i = blockIdx.x * blockDim.x + threadIdx.x;
    if (i < N0n) { finedge_one(esl0, dE0, ep0, ge0, i); return; }
    i -= N0n;
    if (i < N1n) { finedge_one(esl1, dE1, ep1, ge1, i); return; }
    i -= N1n;
    if (i < N2n) { finedge_one(esl2, dE2, ep2, ge2, i); return; }
    i -= N2n;
    if (i < N1n) { sortc_one(csl1, dC1, i); return; }
    i -= N1n;
    if (i < N2n) { sortc_one(csl2, dC2, i); }
}

// ---------------- layer 0: 8-threads-per-node attention, inline radial ----------------
__global__ __launch_bounds__(256) void k_attn0(
    const float* __restrict__ x, const float4* __restrict__ ge, const int* __restrict__ cnt,
    const float* __restrict__ Wq, const float* __restrict__ Wk, const float* __restrict__ Wv,
    const float* __restrict__ Ws, const float* __restrict__ w1, const float* __restrict__ w2,
    const float* __restrict__ scale, const float* __restrict__ bias,
    float* __restrict__ outp, int n, float scl) {
    __shared__ float sGs;
    __shared__ float sw1[16], sw2[16];
    __shared__ float sZ[32];
    __shared__ float sS1[32][3];
    __shared__ float sS2[32][3];
    __shared__ float sXd[32][3];
    int tid = threadIdx.x;
    if (tid == 0) {
        float g = 0.f;
#pragma unroll
        for (int j = 0; j < 32; j++) g += Wq[j] * Wk[j];
        sGs = g * scl;
    }
    if (tid < 16) {
        sw1[tid] = w1[tid];
        sw2[tid] = w2[tid];
    }
    __syncthreads();
    int group = tid >> 3, gl = tid & 7;
    int node = blockIdx.x * 32 + group;
    if (node < n) {
        float Gs = sGs;
        float xd0 = x[node * 3 + 0], xd1 = x[node * 3 + 1], xd2 = x[node * 3 + 2];
        int deg = min(cnt[node], SLOTE);
        int base = node * SLOTE;
        float z = 0.f, s10 = 0.f, s11 = 0.f, s12 = 0.f, s20 = 0.f, s21 = 0.f, s22 = 0.f;
        for (int j = gl; j < deg; j += 8) {
            float4 e = ge[base + j];
            int s = __float_as_int(e.x);
            float xs0 = x[s * 3 + 0], xs1 = x[s * 3 + 1], xs2 = x[s * 3 + 2];
            float rr = sqrtf(e.y * e.y + e.z * e.z + e.w * e.w + 1e-12f);
            float rad = 0.f;
#pragma unroll
            for (int k = 0; k < 16; k++) rad += fmaxf(rr * sw1[k], 0.f) * sw2[k];
            float w = __expf(Gs * (xd0 * xs0 + xd1 * xs1 + xd2 * xs2) + rad);
            z += w;
            s10 += w * xs0;
            s11 += w * xs1;
            s12 += w * xs2;
            s20 += w * e.y;
            s21 += w * e.z;
            s22 += w * e.w;
        }
#pragma unroll
        for (int off = 4; off; off >>= 1) {
            z += __shfl_xor_sync(0xffffffffu, z, off);
            s10 += __shfl_xor_sync(0xffffffffu, s10, off);
            s11 += __shfl_xor_sync(0xffffffffu, s11, off);
            s12 += __shfl_xor_sync(0xffffffffu, s12, off);
            s20 += __shfl_xor_sync(0xffffffffu, s20, off);
            s21 += __shfl_xor_sync(0xffffffffu, s21, off);
            s22 += __shfl_xor_sync(0xffffffffu, s22, off);
        }
        if (gl == 0) {
            sZ[group] = z;
            sS1[group][0] = s10; sS1[group][1] = s11; sS1[group][2] = s12;
            sS2[group][0] = s20; sS2[group][1] = s21; sS2[group][2] = s22;
            sXd[group][0] = xd0; sXd[group][1] = xd1; sXd[group][2] = xd2;
        }
    }
    __syncthreads();
    int warp = tid >> 5, lane = tid & 31;
    float wv = Wv[lane], ws = Ws[lane];
    float sc = scale[lane], bi = bias[lane];
    int blockBase = blockIdx.x * 32;
    for (int i = warp; i < 32; i += 8) {
        int nd = blockBase + i;
        if (nd >= n) break;
        float invz = 1.f / (sZ[i] + 1e-9f);
        float a0 = (wv * sS1[i][0] + sS2[i][0]) * invz + ws * sXd[i][0];
        float a1 = (wv * sS1[i][1] + sS2[i][1]) * invz + ws * sXd[i][1];
        float a2 = (wv * sS1[i][2] + sS2[i][2]) * invz + ws * sXd[i][2];
        float nrm = sqrtf(a0 * a0 + a1 * a1 + a2 * a2 + 1e-12f);
        float t = fmaxf(sc * nrm + bi, 0.f);
        float f = t / nrm;
        *(float4*)(outp + (size_t)nd * XS + lane * 4) =
            make_float4(a0 * f, a1 * f, a2 * f, 0.f);
    }
}

// ---------------- fused attention (Cin=32, inline radial, capped persistent) ----------
template <int Co>
__global__ __launch_bounds__(256) void k_attnF(
    const float* __restrict__ x, const float4* __restrict__ ge, const int* __restrict__ cnt,
    const float* __restrict__ Gbuf, const float* __restrict__ Wq,
    const float* __restrict__ Wk, const float* __restrict__ Wv, const float* __restrict__ Ws,
    const float* __restrict__ w1, const float* __restrict__ w2,
    const float* __restrict__ scale, const float* __restrict__ bias, float* __restrict__ outp,
    int n, float scl) {
    __shared__ float sG[(Co == 32) ? 1024 : 1];
    __shared__ float sWv[(Co == 32) ? 1024 : 1];
    __shared__ float sWs[(Co == 32) ? 1024 : 1];
    __shared__ float sXd[8][(Co == 32) ? 96 : 1];
    __shared__ float sAx[8][(Co == 32) ? 96 : 1];
    int tid = threadIdx.x, warp = tid >> 5, lane = tid & 31;
    if (Co == 32) {
        for (int i = tid; i < 1024; i += 256) {
            sG[i] = Gbuf[i];
            sWv[i] = Wv[i];
            sWs[i] = Ws[i];
        }
        __syncthreads();
    }
    float rw1 = (lane < 16) ? w1[lane] : 0.f;
    float rw2 = (lane < 16) ? w2[lane] : 0.f;
    for (int node = blockIdx.x * 8 + warp; node < n; node += gridDim.x * 8) {
        float4 xd4 = *(const float4*)(x + (size_t)node * XS + lane * 4);
        float xd0 = xd4.x, xd1 = xd4.y, xd2 = xd4.z;
        float q0, q1, q2;
        if (Co == 32) {
            sXd[warp][lane] = xd0;
            sXd[warp][32 + lane] = xd1;
            sXd[warp][64 + lane] = xd2;
            __syncwarp();
            q0 = q1 = q2 = 0.f;
#pragma unroll 8
            for (int c = 0; c < 32; c++) {
                float g = sG[c * 32 + lane];
                q0 += g * sXd[warp][c];
                q1 += g * sXd[warp][32 + c];
                q2 += g * sXd[warp][64 + c];
            }
        } else {
            float wq = Wq[lane];
            float d0 = warp_sum(xd0 * wq);
            float d1 = warp_sum(xd1 * wq);
            float d2 = warp_sum(xd2 * wq);
            float f = scl * Wk[lane];
            q0 = f * d0;
            q1 = f * d1;
            q2 = f * d2;
        }
        int deg = min(cnt[node], SLOTE);
        int base = node * SLOTE;
        float z = 0.f, ax0 = 0.f, ax1 = 0.f, ax2 = 0.f, rs0 = 0.f, rs1 = 0.f, rs2 = 0.f;
        int j = 0;
        for (; j + 4 <= deg; j += 4) {
            float4 e0 = ge[base + j];
            float4 e1 = ge[base + j + 1];
            float4 e2 = ge[base + j + 2];
            float4 e3 = ge[base + j + 3];
            float4 xa = *(const float4*)(x + (size_t)__float_as_int(e0.x) * XS + lane * 4);
            float4 xb = *(const float4*)(x + (size_t)__float_as_int(e1.x) * XS + lane * 4);
            float4 xc = *(const float4*)(x + (size_t)__float_as_int(e2.x) * XS + lane * 4);
            float4 xd = *(const float4*)(x + (size_t)__float_as_int(e3.x) * XS + lane * 4);
            float rr0 = sqrtf(e0.y * e0.y + e0.z * e0.z + e0.w * e0.w + 1e-12f);
            float rr1 = sqrtf(e1.y * e1.y + e1.z * e1.z + e1.w * e1.w + 1e-12f);
            float rr2 = sqrtf(e2.y * e2.y + e2.z * e2.z + e2.w * e2.w + 1e-12f);
            float rr3 = sqrtf(e3.y * e3.y + e3.z * e3.z + e3.w * e3.w + 1e-12f);
            float p0 = q0 * xa.x + q1 * xa.y + q2 * xa.z + fmaxf(rr0 * rw1, 0.f) * rw2;
            float p1 = q0 * xb.x + q1 * xb.y + q2 * xb.z + fmaxf(rr1 * rw1, 0.f) * rw2;
            float p2 = q0 * xc.x + q1 * xc.y + q2 * xc.z + fmaxf(rr2 * rw1, 0.f) * rw2;
            float p3 = q0 * xd.x + q1 * xd.y + q2 * xd.z + fmaxf(rr3 * rw1, 0.f) * rw2;
#pragma unroll
            for (int off = 16; off; off >>= 1) {
                p0 += __shfl_xor_sync(0xffffffffu, p0, off);
                p1 += __shfl_xor_sync(0xffffffffu, p1, off);
                p2 += __shfl_xor_sync(0xffffffffu, p2, off);
                p3 += __shfl_xor_sync(0xffffffffu, p3, off);
            }
            float w0 = __expf(p0), w1f = __expf(p1), w2f = __expf(p2), w3f = __expf(p3);
            z += (w0 + w1f) + (w2f + w3f);
            rs0 += w0 * e0.y + w1f * e1.y + w2f * e2.y + w3f * e3.y;
            rs1 += w0 * e0.z + w1f * e1.z + w2f * e2.z + w3f * e3.z;
            rs2 += w0 * e0.w + w1f * e1.w + w2f * e2.w + w3f * e3.w;
            ax0 += w0 * xa.x + w1f * xb.x + w2f * xc.x + w3f * xd.x;
            ax1 += w0 * xa.y + w1f * xb.y + w2f * xc.y + w3f * xd.y;
            ax2 += w0 * xa.z + w1f * xb.z + w2f * xc.z + w3f * xd.z;
        }
        for (; j < deg; j++) {
            float4 e0 = ge[base + j];
            float4 xa = *(const float4*)(x + (size_t)__float_as_int(e0.x) * XS + lane * 4);
            float rr0 = sqrtf(e0.y * e0.y + e0.z * e0.z + e0.w * e0.w + 1e-12f);
            float p0 = warp_sum(q0 * xa.x + q1 * xa.y + q2 * xa.z +
                                fmaxf(rr0 * rw1, 0.f) * rw2);
            float w0 = __expf(p0);
            z += w0;
            rs0 += w0 * e0.y;
            rs1 += w0 * e0.z;
            rs2 += w0 * e0.w;
            ax0 += w0 * xa.x;
            ax1 += w0 * xa.y;
            ax2 += w0 * xa.z;
        }
        float invz = 1.f / (z + 1e-9f);
        if (Co == 32) {
            sAx[warp][lane] = ax0;
            sAx[warp][32 + lane] = ax1;
            sAx[warp][64 + lane] = ax2;
            __syncwarp();
            float v0 = 0.f, v1 = 0.f, v2 = 0.f, sk0 = 0.f, sk1 = 0.f, sk2 = 0.f;
#pragma unroll 8
            for (int c = 0; c < 32; c++) {
                float wv = sWv[c * 32 + lane];
                float ws = sWs[c * 32 + lane];
                v0 += wv * sAx[warp][c];
                v1 += wv * sAx[warp][32 + c];
                v2 += wv * sAx[warp][64 + c];
                sk0 += ws * sXd[warp][c];
                sk1 += ws * sXd[warp][32 + c];
                sk2 += ws * sXd[warp][64 + c];
            }
            float a0 = (v0 + rs0) * invz + sk0;
            float a1 = (v1 + rs1) * invz + sk1;
            float a2 = (v2 + rs2) * invz + sk2;
            float sc = scale[lane], bi = bias[lane];
            float nrm = sqrtf(a0 * a0 + a1 * a1 + a2 * a2 + 1e-12f);
            float t = fmaxf(sc * nrm + bi, 0.f);
            float f = t / nrm;
            *(float4*)(outp + (size_t)node * XS + lane * 4) =
                make_float4(a0 * f, a1 * f, a2 * f, 0.f);
            __syncwarp();
        } else {
            float wv = Wv[lane], ws = Ws[lane];
            float v0 = warp_sum(wv * ax0);
            float v1 = warp_sum(wv * ax1);
            float v2 = warp_sum(wv * ax2);
            float sk0 = warp_sum(ws * xd0);
            float sk1 = warp_sum(ws * xd1);
            float sk2 = warp_sum(ws * xd2);
            if (lane == 0) {
                float a0 = (v0 + rs0) * invz + sk0;
                float a1 = (v1 + rs1) * invz + sk1;
                float a2 = (v2 + rs2) * invz + sk2;
                float sc = scale[0], bi = bias[0];
                float nrm = sqrtf(a0 * a0 + a1 * a1 + a2 * a2 + 1e-12f);
                float t = fmaxf(sc * nrm + bi, 0.f);
                float f = t / nrm;
                outp[node * 3 + 0] = a0 * f;
                outp[node * 3 + 1] = a1 * f;
                outp[node * 3 + 2] = a2 * f;
            }
        }
    }
}

// ---------------- pooling / upsample / head ----------------
__global__ void k_segmean(const float* __restrict__ xin, const int* __restrict__ cnt,
                          const int* __restrict__ csl, float* __restrict__ outp, int nseg) {
    int warp = (blockIdx.x * blockDim.x + threadIdx.x) >> 5;
    int lane = threadIdx.x & 31;
    if (warp >= nseg) return;
    int deg = min(cnt[warp], SLOTC);
    int base = warp * SLOTC;
    float a0 = 0.f, a1 = 0.f, a2 = 0.f;
    for (int j = 0; j < deg; j++) {
        int mnode = csl[base + j];
        float4 xv = *(const float4*)(xin + (size_t)mnode * XS + lane * 4);
        a0 += xv.x;
        a1 += xv.y;
        a2 += xv.z;
    }
    float inv = 1.f / ((float)deg + 1e-9f);
    *(float4*)(outp + (size_t)warp * XS + lane * 4) =
        make_float4(a0 * inv, a1 * inv, a2 * inv, 0.f);
}

__global__ void k_upsample(float* __restrict__ outp, const float* __restrict__ basep,
                           const int* __restrict__ inv, const float* __restrict__ xup,
                           int n) {
    int i = blockIdx.x * blockDim.x + threadIdx.x;
    if (i >= n * XS) return;
    int node = i >> 7, t = i & (XS - 1);
    int s = inv[node];
    float v = basep[i];
    if (s >= 0) v += xup[(size_t)s * XS + t];
    outp[i] = v;
}

__global__ void k_mlp(const float* __restrict__ xin, const float* __restrict__ W,
                      float* __restrict__ outp, int n) {
    int i = blockIdx.x * blockDim.x + threadIdx.x;
    if (i >= n * 40) return;
    int node = i / 40, o = i % 40;
    float s = xin[node * 3 + 0] * W[o] + xin[node * 3 + 1] * W[40 + o] +
              xin[node * 3 + 2] * W[80 + o];
    outp[i] = s > 0.f ? s : 0.f;
}

// ---------------- host orchestration ----------------
#define GETSYM(p, s)                  \
    do {                              \
        void* _t;                     \
        cudaGetSymbolAddress(&_t, s); \
        p = (decltype(p))_t;          \
    } while (0)

extern "C" void kernel_launch(void* const* d_in, const int* in_sizes, int n_in,
                              void* d_out, int out_size) {
    const float* pos0 = (const float*)d_in[0];
    const float* v0 = (const float*)d_in[1];
    const float* Wq_first = (const float*)d_in[2];
    const float* Wk_first = (const float*)d_in[3];
    const float* Wv_first = (const float*)d_in[4];
    const float* Ws_first = (const float*)d_in[5];
    const float* Wq_mid = (const float*)d_in[6];
    const float* Wk_mid = (const float*)d_in[7];
    const float* Wv_mid = (const float*)d_in[8];
    const float* Ws_mid = (const float*)d_in[9];
    const float* Wq_last = (const float*)d_in[10];
    const float* Wk_last = (const float*)d_in[11];
    const float* Wv_last = (const float*)d_in[12];
    const float* Ws_last = (const float*)d_in[13];
    const float* wr1 = (const float*)d_in[14];
    const float* wr2 = (const float*)d_in[15];
    const float* scale_mid = (const float*)d_in[16];
    const float* bias_mid = (const float*)d_in[17];
    const float* scale_last = (const float*)d_in[18];
    const float* bias_last = (const float*)d_in[19];
    const float* Wmlp = (const float*)d_in[20];
    const int* src0 = (const int*)d_in[21];
    const int* dst0 = (const int*)d_in[22];
    const int* src1 = (const int*)d_in[23];
    const int* dst1 = (const int*)d_in[24];
    const int* src2 = (const int*)d_in[25];
    const int* dst2 = (const int*)d_in[26];
    const int* fp1 = (const int*)d_in[27];
    const int* fp2 = (const int*)d_in[28];
    const int* cl1 = (const int*)d_in[29];
    const int* cl2 = (const int*)d_in[30];
    float* outp = (float*)d_out;

    float *xA, *xB, *x0s, *x1s, *pos1, *pos2, *Gb;
    float4 *ep0, *ep1, *ep2, *ge0, *ge1, *ge2;
    int *cnts, *esl0, *esl1, *esl2, *csl1, *csl2, *inv1, *inv2;
    GETSYM(xA, g_xA); GETSYM(xB, g_xB); GETSYM(x0s, g_x0s); GETSYM(x1s, g_x1s);
    GETSYM(pos1, g_pos1); GETSYM(pos2, g_pos2); GETSYM(Gb, g_G);
    GETSYM(ep0, g_ep0); GETSYM(ep1, g_ep1); GETSYM(ep2, g_ep2);
    GETSYM(ge0, g_ge0); GETSYM(ge1, g_ge1); GETSYM(ge2, g_ge2);
    GETSYM(esl0, g_esl0); GETSYM(esl1, g_esl1); GETSYM(esl2, g_esl2);
    GETSYM(csl1, g_csl1); GETSYM(csl2, g_csl2);
    GETSYM(cnts, g_cnts); GETSYM(inv1, g_inv1); GETSYM(inv2, g_inv2);

    int* dE0 = cnts;
    int* dE1 = cnts + N0n;
    int* dE2 = cnts + N0n + N1n;
    int* dC1 = cnts + N0n + N1n + N2n;
    int* dC2 = cnts + N0n + N1n + N2n + N1n;
    const int nCnt = N0n + N1n + N2n + N1n + N2n;

    const float scl_mid = 0.10206207261596575f;  // 1/sqrt(96)
    const float scl_last = 0.5773502691896258f;  // 1/sqrt(3)
    auto midW = [&](const float* base, int i) { return base + i * 32 * 32; };

    // ---- build: 3 launches ----
    {
        int tot = nCnt + N0n + N1n + 8 * 1024 + N1n * 3 + N2n * 3;
        k_pre<<<(tot + 255) / 256, 256>>>(Wq_mid, Wk_mid, Gb, pos0, fp1, fp2, pos1, pos2,
                                          cnts, inv1, inv2, scl_mid);
    }
    {
        int tot = E0n + E1n + E2n + N0n + N1n + E0n + E1n + E2n + N1n + N2n;
        k_scat_eg<<<(tot + 255) / 256, 256>>>(dst0, dst1, dst2, cl1, cl2, dE0, dE1, dE2,
                                              dC1, dC2, esl0, esl1, esl2, csl1, csl2, pos0,
                                              pos1, pos2, src0, src1, src2, ep0, ep1, ep2,
                                              fp1, fp2, inv1, inv2);
    }
    {
        int tot = N0n + N1n + N2n + N1n + N2n;
        k_finsort_all<<<(tot + 255) / 256, 256>>>(esl0, esl1, esl2, csl1, csl2, dE0, dE1,
                                                  dE2, dC1, dC2, ep0, ep1, ep2, ge0, ge1,
                                                  ge2);
    }

    // ---- layer 0 (launch index 3 — ncu capture target; 8 threads/node) ----
    k_attn0<<<(N0n + 31) / 32, 256>>>(v0, ge0, dE0, Wq_first, Wk_first, Wv_first, Ws_first,
                                      wr1 + 0, wr2 + 0, scale_mid + 0, bias_mid + 0, xA,
                                      N0n, scl_mid);

    struct LD {
        int n;
        const int* cnt;
        const float4* ge;
        const float *Gq, *Wq, *Wk, *Wv, *Ws, *sc, *bi, *w1, *w2;
        const float* xin;
        float* xout;
        float scl;
        int co;
    };
    LD L[10];
    L[1] = {N0n, dE0, ge0, Gb + 0 * 1024, midW(Wq_mid, 0), midW(Wk_mid, 0), midW(Wv_mid, 0),
            midW(Ws_mid, 0), scale_mid + 32, bias_mid + 32, wr1 + 16, wr2 + 16, xA, x0s,
            scl_mid, 32};
    L[2] = {N1n, dE1, ge1, Gb + 1 * 1024, midW(Wq_mid, 1), midW(Wk_mid, 1), midW(Wv_mid, 1),
            midW(Ws_mid, 1), scale_mid + 64, bias_mid + 64, wr1 + 32, wr2 + 32, xA, xB,
            scl_mid, 32};
    L[3] = {N1n, dE1, ge1, Gb + 2 * 1024, midW(Wq_mid, 2), midW(Wk_mid, 2), midW(Wv_mid, 2),
            midW(Ws_mid, 2), scale_mid + 96, bias_mid + 96, wr1 + 48, wr2 + 48, xB, x1s,
            scl_mid, 32};
    L[4] = {N2n, dE2, ge2, Gb + 3 * 1024, midW(Wq_mid, 3), midW(Wk_mid, 3), midW(Wv_mid, 3),
            midW(Ws_mid, 3), scale_mid + 128, bias_mid + 128, wr1 + 64, wr2 + 64, xA, xB,
            scl_mid, 32};
    L[5] = {N2n, dE2, ge2, Gb + 4 * 1024, midW(Wq_mid, 4), midW(Wk_mid, 4), midW(Wv_mid, 4),
            midW(Ws_mid, 4), scale_mid + 160, bias_mid + 160, wr1 + 80, wr2 + 80, xB, xA,
            scl_mid, 32};
    L[6] = {N1n, dE1, ge1, Gb + 5 * 1024, midW(Wq_mid, 5), midW(Wk_mid, 5), midW(Wv_mid, 5),
            midW(Ws_mid, 5), scale_mid + 192, bias_mid + 192, wr1 + 96, wr2 + 96, xB, xA,
            scl_mid, 32};
    L[7] = {N1n, dE1, ge1, Gb + 6 * 1024, midW(Wq_mid, 6), midW(Wk_mid, 6), midW(Wv_mid, 6),
            midW(Ws_mid, 6), scale_mid + 224, bias_mid + 224, wr1 + 112, wr2 + 112, xA, xB,
            scl_mid, 32};
    L[8] = {N0n, dE0, ge0, Gb + 7 * 1024, midW(Wq_mid, 7), midW(Wk_mid, 7), midW(Wv_mid, 7),
            midW(Ws_mid, 7), scale_mid + 256, bias_mid + 256, wr1 + 128, wr2 + 128, xA, xB,
            scl_mid, 32};
    L[9] = {N0n, dE0, ge0, Gb, Wq_last, Wk_last, Wv_last, Ws_last, scale_last, bias_last,
            wr1 + 144, wr2 + 144, xB, xA, scl_last, 1};

    auto run_layer = [&](const LD& d) {
        int want = (d.n + 7) / 8;
        int blk = want < 1184 ? want : 1184;
        if (d.co == 32) {
            k_attnF<32><<<blk, 256>>>(d.xin, d.ge, d.cnt, d.Gq, d.Wq, d.Wk, d.Wv, d.Ws,
                                      d.w1, d.w2, d.sc, d.bi, d.xout, d.n, d.scl);
        } else {
            k_attnF<1><<<blk, 256>>>(d.xin, d.ge, d.cnt, d.Gq, d.Wq, d.Wk, d.Wv, d.Ws,
                                     d.w1, d.w2, d.sc, d.bi, d.xout, d.n, d.scl);
        }
    };

    run_layer(L[1]);  // -> x0s
    k_segmean<<<(N1n + 7) / 8, 256>>>(x0s, dC1, csl1, xA, N1n);
    run_layer(L[2]);
    run_layer(L[3]);  // -> x1s
    k_segmean<<<(N2n + 7) / 8, 256>>>(x1s, dC2, csl2, xA, N2n);
    run_layer(L[4]);
    run_layer(L[5]);  // -> xA (N2)
    k_upsample<<<(N1n * XS + 255) / 256, 256>>>(xB, x1s, inv2, xA, N1n);
    run_layer(L[6]);
    run_layer(L[7]);  // -> xB (N1)
    k_upsample<<<(N0n * XS + 255) / 256, 256>>>(xA, x0s, inv1, xB, N0n);
    run_layer(L[8]);
    run_layer(L[9]);  // -> xA [N0,3]
    k_mlp<<<(N0n * 40 + 255) / 256, 256>>>(xA, Wmlp, outp, N0n);
}